// round 2
// baseline (speedup 1.0000x reference)
#include <cuda_runtime.h>

// Problem constants
#define T_SEQ   4096
#define D_MODEL 512
#define N_HEADS 8
#define D_K     64
#define BATCH   2
#define BH      (BATCH * N_HEADS)       // 16
#define M_ROWS  (BATCH * T_SEQ)         // 8192

// Intermediates: head-major layout [BH][T][64] for q,k,v; [M][512] for attn out.
__device__ float g_q[(size_t)BH * T_SEQ * D_K];
__device__ float g_k[(size_t)BH * T_SEQ * D_K];
__device__ float g_v[(size_t)BH * T_SEQ * D_K];
__device__ float g_o[(size_t)M_ROWS * D_MODEL];

// ---------------------------------------------------------------------------
// Generic GEMM: C[m,n] = sum_k A[m,k] * W[n,k] + bias[n]
// A: [M,512] row-major (K contiguous), W: [512,512] row-major (K contiguous).
// mode 0/1/2: write to g_q/g_k/g_v in [BH][T][64] head layout (tile N==head).
// mode 3:     write to Cflat[m*512 + n].
// A == nullptr -> read from g_o (for the output projection).
// Tiling: 64x64 per CTA, 128 threads, each thread computes 4 rows x 8 cols.
// Thread (tx,ty) owns rows ty*4..+3 and columns {tx + 8*j} (stride-8 cols ->
// conflict-free scalar smem reads and contiguous warp-level global stores).
// ---------------------------------------------------------------------------
__global__ __launch_bounds__(128)
void gemm_bias_kernel(const float* __restrict__ A,
                      const float* __restrict__ W,
                      const float* __restrict__ bias,
                      float* __restrict__ Cflat,
                      int mode)
{
    __shared__ float As[32 * 65];   // [k][m], stride 65 (conflict-free writes)
    __shared__ float Bs[32 * 65];   // [k][n], stride 65

    const float* Ap = A ? A : g_o;
    float* dst = (mode == 0) ? g_q : (mode == 1) ? g_k : (mode == 2) ? g_v : Cflat;

    const int tid = threadIdx.x;
    const int tx  = tid & 7;        // 0..7  (n sub-tile)
    const int ty  = tid >> 3;       // 0..15 (m sub-tile)
    const int m0  = blockIdx.y * 64;
    const int n0  = blockIdx.x * 64;

    const int lk4 = tid & 7;        // k float4 index 0..7
    const int lr  = tid >> 3;       // row base 0..15

    float acc[4][8];
#pragma unroll
    for (int i = 0; i < 4; i++)
#pragma unroll
        for (int j = 0; j < 8; j++) acc[i][j] = 0.0f;

    for (int kt = 0; kt < D_MODEL; kt += 32) {
        // Load 64x32 tiles of A and W, transposed into smem [k][m]/[k][n].
        // Write bank = (4*lk4 + c + r) mod 32 -> all 32 lanes distinct: conflict-free.
#pragma unroll
        for (int i = 0; i < 4; i++) {
            int r = lr + 16 * i;
            float4 va = *(const float4*)&Ap[(size_t)(m0 + r) * D_MODEL + kt + 4 * lk4];
            As[(4 * lk4 + 0) * 65 + r] = va.x;
            As[(4 * lk4 + 1) * 65 + r] = va.y;
            As[(4 * lk4 + 2) * 65 + r] = va.z;
            As[(4 * lk4 + 3) * 65 + r] = va.w;
            float4 vw = *(const float4*)&W[(size_t)(n0 + r) * D_MODEL + kt + 4 * lk4];
            Bs[(4 * lk4 + 0) * 65 + r] = vw.x;
            Bs[(4 * lk4 + 1) * 65 + r] = vw.y;
            Bs[(4 * lk4 + 2) * 65 + r] = vw.z;
            Bs[(4 * lk4 + 3) * 65 + r] = vw.w;
        }
        __syncthreads();

#pragma unroll 4
        for (int kk = 0; kk < 32; kk++) {
            float av[4], bv[8];
#pragma unroll
            for (int i = 0; i < 4; i++) av[i] = As[kk * 65 + ty * 4 + i];   // broadcast, no conflict
#pragma unroll
            for (int j = 0; j < 8; j++) bv[j] = Bs[kk * 65 + tx + 8 * j];   // 8 distinct banks
#pragma unroll
            for (int i = 0; i < 4; i++)
#pragma unroll
                for (int j = 0; j < 8; j++)
                    acc[i][j] += av[i] * bv[j];
        }
        __syncthreads();
    }

    // Epilogue
    if (mode < 3) {
        // head layout: dst[((b*8 + h)*T + t)*64 + d], h == blockIdx.x, d = tx + 8j
#pragma unroll
        for (int i = 0; i < 4; i++) {
            int m = m0 + ty * 4 + i;
            int b = m >> 12;
            int t = m & (T_SEQ - 1);
            float* o = &dst[(((size_t)(b * N_HEADS + blockIdx.x)) * T_SEQ + t) * D_K];
#pragma unroll
            for (int j = 0; j < 8; j++)
                o[tx + 8 * j] = acc[i][j] + bias[n0 + tx + 8 * j];
        }
    } else {
#pragma unroll
        for (int i = 0; i < 4; i++) {
            int m = m0 + ty * 4 + i;
            float* o = &Cflat[(size_t)m * D_MODEL + n0];
#pragma unroll
            for (int j = 0; j < 8; j++)
                o[tx + 8 * j] = acc[i][j] + bias[n0 + tx + 8 * j];
        }
    }
}

// ---------------------------------------------------------------------------
// Flash attention (fp32). One CTA = one (b,h) x 64 query rows.
// 128 threads, thread grid 16(ty) x 8(tx); each thread owns rows ty*4..+3
// and tile columns {tx + 8*j}. The 8 owners of a row are lanes differing
// only in bits 0..2 -> shfl_xor{1,2,4} row reductions.
//
// All three smem tiles are 64x64 stride-64 (48KB total = static limit,
// 4 CTAs/SM) with a rotation swizzle SWZ(row,col) = row*64 + ((col+row)&63):
//  - transposed Q/K stores and P^T stores drop from 16-/8-way conflicts to <=2-way
//  - all inner-loop scalar reads remain conflict-free broadcasts
// ---------------------------------------------------------------------------
#define SWZ(row, col) ((row) * 64 + (((col) + (row)) & 63))

__global__ __launch_bounds__(128)
void attn_kernel()
{
    __shared__ float Qs [64 * 64];   // [d][m]   (Q^T, pre-scaled)
    __shared__ float KVs[64 * 64];   // K: [d][key]  then  V: [key][d]
    __shared__ float Ps [64 * 64];   // [key][m] (P^T)

    const int tid = threadIdx.x;
    const int tx  = tid & 7;
    const int ty  = tid >> 3;
    const int bh  = blockIdx.y;
    const int qt  = blockIdx.x;

    const float* Qp = g_q + (size_t)bh * T_SEQ * D_K + (size_t)qt * 64 * D_K;
    const float* Kb = g_k + (size_t)bh * T_SEQ * D_K;
    const float* Vb = g_v + (size_t)bh * T_SEQ * D_K;

    const int lc4 = tid & 15;   // d float4 index 0..15
    const int lr0 = tid >> 4;   // row base 0..7

    // Load Q tile transposed (row=d, col=m), pre-scaled by 1/sqrt(d_k)
#pragma unroll
    for (int i = 0; i < 8; i++) {
        int r = lr0 + 8 * i;
        float4 v = *(const float4*)&Qp[r * D_K + 4 * lc4];
        Qs[SWZ(4 * lc4 + 0, r)] = v.x * 0.125f;
        Qs[SWZ(4 * lc4 + 1, r)] = v.y * 0.125f;
        Qs[SWZ(4 * lc4 + 2, r)] = v.z * 0.125f;
        Qs[SWZ(4 * lc4 + 3, r)] = v.w * 0.125f;
    }

    float acc[4][8];
    float mrow[4], lrow[4];
#pragma unroll
    for (int i = 0; i < 4; i++) {
        mrow[i] = -1e30f;
        lrow[i] = 0.0f;
#pragma unroll
        for (int j = 0; j < 8; j++) acc[i][j] = 0.0f;
    }

    for (int kt = 0; kt < T_SEQ / 64; kt++) {
        const float* Kp = Kb + (size_t)kt * 64 * D_K;
        const float* Vp = Vb + (size_t)kt * 64 * D_K;

        __syncthreads();   // prev iter's GEMM2 done with KVs/Ps (and Q ready, iter 0)

        // Load K tile transposed -> KVs as [d][key]
#pragma unroll
        for (int i = 0; i < 8; i++) {
            int r = lr0 + 8 * i;
            float4 v = *(const float4*)&Kp[r * D_K + 4 * lc4];
            KVs[SWZ(4 * lc4 + 0, r)] = v.x;
            KVs[SWZ(4 * lc4 + 1, r)] = v.y;
            KVs[SWZ(4 * lc4 + 2, r)] = v.z;
            KVs[SWZ(4 * lc4 + 3, r)] = v.w;
        }
        __syncthreads();

        // GEMM1: S = (Q/8) K^T, contracting over d (= smem row kk)
        float s[4][8];
#pragma unroll
        for (int i = 0; i < 4; i++)
#pragma unroll
            for (int j = 0; j < 8; j++) s[i][j] = 0.0f;

#pragma unroll 4
        for (int kk = 0; kk < 64; kk++) {
            float av[4], bv[8];
#pragma unroll
            for (int i = 0; i < 4; i++) av[i] = Qs[SWZ(kk, ty * 4 + i)];
#pragma unroll
            for (int j = 0; j < 8; j++) bv[j] = KVs[SWZ(kk, tx + 8 * j)];
#pragma unroll
            for (int i = 0; i < 4; i++)
#pragma unroll
                for (int j = 0; j < 8; j++)
                    s[i][j] += av[i] * bv[j];
        }

        // Online softmax update (registers + shfl only); key index of s[i][j] = tx+8j
#pragma unroll
        for (int i = 0; i < 4; i++) {
            float tm = s[i][0];
#pragma unroll
            for (int j = 1; j < 8; j++) tm = fmaxf(tm, s[i][j]);
            tm = fmaxf(tm, __shfl_xor_sync(0xffffffffu, tm, 1));
            tm = fmaxf(tm, __shfl_xor_sync(0xffffffffu, tm, 2));
            tm = fmaxf(tm, __shfl_xor_sync(0xffffffffu, tm, 4));
            float mnew = fmaxf(mrow[i], tm);
            float corr = __expf(mrow[i] - mnew);
            mrow[i] = mnew;
            float rs = 0.0f;
#pragma unroll
            for (int j = 0; j < 8; j++) {
                float p = __expf(s[i][j] - mnew);
                s[i][j] = p;
                rs += p;
            }
            rs += __shfl_xor_sync(0xffffffffu, rs, 1);
            rs += __shfl_xor_sync(0xffffffffu, rs, 2);
            rs += __shfl_xor_sync(0xffffffffu, rs, 4);
            lrow[i] = lrow[i] * corr + rs;
#pragma unroll
            for (int j = 0; j < 8; j++) acc[i][j] *= corr;
        }

        __syncthreads();   // everyone done reading KVs as K

        // Store P^T -> Ps [key][m]; load V -> KVs as [key][d]
#pragma unroll
        for (int i = 0; i < 4; i++)
#pragma unroll
            for (int j = 0; j < 8; j++)
                Ps[SWZ(tx + 8 * j, ty * 4 + i)] = s[i][j];
#pragma unroll
        for (int i = 0; i < 8; i++) {
            int r = lr0 + 8 * i;
            float4 v = *(const float4*)&Vp[r * D_K + 4 * lc4];
            KVs[SWZ(r, 4 * lc4 + 0)] = v.x;
            KVs[SWZ(r, 4 * lc4 + 1)] = v.y;
            KVs[SWZ(r, 4 * lc4 + 2)] = v.z;
            KVs[SWZ(r, 4 * lc4 + 3)] = v.w;
        }
        __syncthreads();

        // GEMM2: acc += P V, contracting over key (= smem row kk)
#pragma unroll 4
        for (int kk = 0; kk < 64; kk++) {
            float av[4], bv[8];
#pragma unroll
            for (int i = 0; i < 4; i++) av[i] = Ps[SWZ(kk, ty * 4 + i)];
#pragma unroll
            for (int j = 0; j < 8; j++) bv[j] = KVs[SWZ(kk, tx + 8 * j)];
#pragma unroll
            for (int i = 0; i < 4; i++)
#pragma unroll
                for (int j = 0; j < 8; j++)
                    acc[i][j] += av[i] * bv[j];
        }
    }

    // Epilogue: normalize and write [B,T,H*64] concat layout to g_o; d = tx+8j
    const int b = bh >> 3;
    const int h = bh & 7;
#pragma unroll
    for (int i = 0; i < 4; i++) {
        int t = qt * 64 + ty * 4 + i;
        float inv = 1.0f / lrow[i];
        float* o = &g_o[((size_t)(b * T_SEQ + t)) * D_MODEL + h * D_K];
#pragma unroll
        for (int j = 0; j < 8; j++)
            o[tx + 8 * j] = acc[i][j] * inv;
    }
}

// ---------------------------------------------------------------------------
// Launch: QKV projections -> flash attention -> output projection.
// Inputs (metadata order): x, Wq, bq, Wk, bk, Wv, bv, Wo, bo. Output fp32.
// ---------------------------------------------------------------------------
extern "C" void kernel_launch(void* const* d_in, const int* in_sizes, int n_in,
                              void* d_out, int out_size)
{
    const float* x  = (const float*)d_in[0];
    const float* Wq = (const float*)d_in[1];
    const float* bq = (const float*)d_in[2];
    const float* Wk = (const float*)d_in[3];
    const float* bk = (const float*)d_in[4];
    const float* Wv = (const float*)d_in[5];
    const float* bv = (const float*)d_in[6];
    const float* Wo = (const float*)d_in[7];
    const float* bo = (const float*)d_in[8];
    float* out = (float*)d_out;

    dim3 gproj(D_MODEL / 64, M_ROWS / 64, 1);   // (8, 128)
    dim3 blk(128, 1, 1);

    gemm_bias_kernel<<<gproj, blk>>>(x, Wq, bq, nullptr, 0);
    gemm_bias_kernel<<<gproj, blk>>>(x, Wk, bk, nullptr, 1);
    gemm_bias_kernel<<<gproj, blk>>>(x, Wv, bv, nullptr, 2);

    dim3 gattn(T_SEQ / 64, BH, 1);              // (64, 16)
    attn_kernel<<<gattn, blk>>>();

    gemm_bias_kernel<<<gproj, blk>>>(nullptr, Wo, bo, out, 3);
}

// round 5
// speedup vs baseline: 5.0314x; 5.0314x over previous
#include <cuda_runtime.h>
#include <cuda_fp16.h>

// Problem constants
#define T_SEQ   4096
#define D_MODEL 512
#define N_HEADS 8
#define D_K     64
#define BATCH   2
#define BH      (BATCH * N_HEADS)       // 16
#define M_ROWS  (BATCH * T_SEQ)         // 8192
#define NTILES  (T_SEQ / 64)            // 64 key tiles

// Q is pre-scaled by 0.125 * log2(e) so softmax runs in base-2 domain.
#define QSCALE  (0.125f * 1.44269504088896f)

// Intermediates
__device__ __half g_qh[(size_t)BH * T_SEQ * D_K];   // [bh][t][64] f16 (pre-scaled)
__device__ __half g_kh[(size_t)BH * T_SEQ * D_K];   // [bh][t][64] f16
__device__ __half g_vh[(size_t)BH * T_SEQ * D_K];   // [bh][t][64] f16
__device__ float  g_o [(size_t)M_ROWS * D_MODEL];   // attention output fp32

// ===========================================================================
// Small helpers
// ===========================================================================
__device__ __forceinline__ unsigned smem_u32(const void* p) {
    unsigned a;
    asm("{ .reg .u64 t; cvta.to.shared.u64 t, %1; cvt.u32.u64 %0, t; }" : "=r"(a) : "l"(p));
    return a;
}
__device__ __forceinline__ float fast_exp2(float x) {
    float y;
    asm("ex2.approx.ftz.f32 %0, %1;" : "=f"(y) : "f"(x));
    return y;
}
// Row-major [row][64 halfs] tile with XOR swizzle on 16B chunks:
// byte offset of (row, chunk) = row*128 + (chunk ^ (row&7))*16
__device__ __forceinline__ unsigned swz(int row, int ch) {
    return (unsigned)(row * 128 + ((ch ^ (row & 7)) << 4));
}
__device__ __forceinline__ void ldm_x4(unsigned addr, unsigned& r0, unsigned& r1,
                                       unsigned& r2, unsigned& r3) {
    asm volatile("ldmatrix.sync.aligned.m8n8.x4.shared.b16 {%0,%1,%2,%3}, [%4];"
                 : "=r"(r0), "=r"(r1), "=r"(r2), "=r"(r3) : "r"(addr));
}
__device__ __forceinline__ void ldm_x4_t(unsigned addr, unsigned& r0, unsigned& r1,
                                         unsigned& r2, unsigned& r3) {
    asm volatile("ldmatrix.sync.aligned.m8n8.x4.trans.shared.b16 {%0,%1,%2,%3}, [%4];"
                 : "=r"(r0), "=r"(r1), "=r"(r2), "=r"(r3) : "r"(addr));
}
__device__ __forceinline__ void mma16816(float* c, const unsigned* a,
                                         unsigned b0, unsigned b1) {
    asm volatile(
        "mma.sync.aligned.m16n8k16.row.col.f32.f16.f16.f32 "
        "{%0,%1,%2,%3}, {%4,%5,%6,%7}, {%8,%9}, {%0,%1,%2,%3};"
        : "+f"(c[0]), "+f"(c[1]), "+f"(c[2]), "+f"(c[3])
        : "r"(a[0]), "r"(a[1]), "r"(a[2]), "r"(a[3]), "r"(b0), "r"(b1));
}

// ===========================================================================
// fp32 projection GEMM: C[m,n] = sum_k A[m,k] * W[n,k] + bias[n]
// mode 0: -> g_qh f16 [bh][t][64], scaled by QSCALE
// mode 1: -> g_kh f16 [bh][t][64]
// mode 2: -> g_vh f16 [bh][t][64]
// mode 3: -> Cflat fp32 [m][512]   (A=nullptr -> read g_o)
// ===========================================================================
__global__ __launch_bounds__(128)
void gemm_bias_kernel(const float* __restrict__ A,
                      const float* __restrict__ W,
                      const float* __restrict__ bias,
                      float* __restrict__ Cflat,
                      int mode)
{
    __shared__ float As[32 * 65];
    __shared__ float Bs[32 * 65];

    const float* Ap = A ? A : g_o;

    const int tid = threadIdx.x;
    const int tx  = tid & 7;
    const int ty  = tid >> 3;
    const int m0  = blockIdx.y * 64;
    const int n0  = blockIdx.x * 64;
    const int lk4 = tid & 7;
    const int lr  = tid >> 3;

    float acc[4][8];
#pragma unroll
    for (int i = 0; i < 4; i++)
#pragma unroll
        for (int j = 0; j < 8; j++) acc[i][j] = 0.0f;

    for (int kt = 0; kt < D_MODEL; kt += 32) {
#pragma unroll
        for (int i = 0; i < 4; i++) {
            int r = lr + 16 * i;
            float4 va = *(const float4*)&Ap[(size_t)(m0 + r) * D_MODEL + kt + 4 * lk4];
            As[(4 * lk4 + 0) * 65 + r] = va.x;
            As[(4 * lk4 + 1) * 65 + r] = va.y;
            As[(4 * lk4 + 2) * 65 + r] = va.z;
            As[(4 * lk4 + 3) * 65 + r] = va.w;
            float4 vw = *(const float4*)&W[(size_t)(n0 + r) * D_MODEL + kt + 4 * lk4];
            Bs[(4 * lk4 + 0) * 65 + r] = vw.x;
            Bs[(4 * lk4 + 1) * 65 + r] = vw.y;
            Bs[(4 * lk4 + 2) * 65 + r] = vw.z;
            Bs[(4 * lk4 + 3) * 65 + r] = vw.w;
        }
        __syncthreads();

#pragma unroll 4
        for (int kk = 0; kk < 32; kk++) {
            float av[4], bv[8];
#pragma unroll
            for (int i = 0; i < 4; i++) av[i] = As[kk * 65 + ty * 4 + i];
#pragma unroll
            for (int j = 0; j < 8; j++) bv[j] = Bs[kk * 65 + tx + 8 * j];
#pragma unroll
            for (int i = 0; i < 4; i++)
#pragma unroll
                for (int j = 0; j < 8; j++)
                    acc[i][j] += av[i] * bv[j];
        }
        __syncthreads();
    }

    const int h = blockIdx.x;   // head index for modes 0..2 (n0 = h*64)
    if (mode <= 2) {
        __half* dst = (mode == 0) ? g_qh : (mode == 1) ? g_kh : g_vh;
        const float sc = (mode == 0) ? QSCALE : 1.0f;
#pragma unroll
        for (int i = 0; i < 4; i++) {
            int m = m0 + ty * 4 + i;
            int b = m >> 12;
            int t = m & (T_SEQ - 1);
            __half* o = &dst[(((size_t)(b * N_HEADS + h)) * T_SEQ + t) * D_K];
#pragma unroll
            for (int j = 0; j < 8; j++)
                o[tx + 8 * j] = __float2half_rn((acc[i][j] + bias[n0 + tx + 8 * j]) * sc);
        }
    } else {
#pragma unroll
        for (int i = 0; i < 4; i++) {
            int m = m0 + ty * 4 + i;
            float* o = &Cflat[(size_t)m * D_MODEL + n0];
#pragma unroll
            for (int j = 0; j < 8; j++)
                o[tx + 8 * j] = acc[i][j] + bias[n0 + tx + 8 * j];
        }
    }
}

// ===========================================================================
// mma.sync f16 flash attention.
// CTA = 128 queries x one (b,h); 4 warps, warp w owns query rows 32w..32w+31
// (two m16 tiles). Key tiles of 64. Per tile:
//   MMA1: S[32x64] = Q * K^T          (16 m16n8k16 per k-step, 4 k-steps)
//   online softmax (base-2, fp32 regs, quad shfl reductions)
//   S C-frags repacked in-register as P A-frags
//   MMA2: O[32x64] += P * V
// K/V double-buffered in smem; next tile's LDGs issued before MMA1.
// ===========================================================================
__global__ __launch_bounds__(128)
void attn_mma_kernel()
{
    __shared__ __half sQ[128 * 64];        // 16 KB
    __shared__ __half sK[2][64 * 64];      // 16 KB
    __shared__ __half sV[2][64 * 64];      // 16 KB   (total 48 KB)

    const int tid  = threadIdx.x;
    const int w    = tid >> 5;
    const int lane = tid & 31;
    const int gid  = lane >> 2;    // group id (row within 8)
    const int tig  = lane & 3;     // thread in group (col pair)
    const int bh   = blockIdx.y;
    const int qt   = blockIdx.x;

    const __half* Qp = g_qh + (size_t)bh * T_SEQ * D_K + (size_t)qt * 128 * D_K;
    const __half* Kb = g_kh + (size_t)bh * T_SEQ * D_K;
    const __half* Vb = g_vh + (size_t)bh * T_SEQ * D_K;

    const unsigned bQ = smem_u32(sQ);
    const unsigned bK0 = smem_u32(sK[0]), bK1 = smem_u32(sK[1]);
    const unsigned bV0 = smem_u32(sV[0]), bV1 = smem_u32(sV[1]);

    // ---- Load Q (128 rows x 8 chunks = 1024 uint4; 8 per thread) ----
#pragma unroll
    for (int i = 0; i < 8; i++) {
        int g = tid + 128 * i;
        int row = g >> 3, ch = g & 7;
        uint4 v = *(const uint4*)(Qp + row * D_K + ch * 8);
        *(uint4*)((char*)sQ + swz(row, ch)) = v;
    }
    // ---- Load K/V tile 0 into buffer 0 ----
#pragma unroll
    for (int i = 0; i < 4; i++) {
        int g = tid + 128 * i;
        int row = g >> 3, ch = g & 7;
        *(uint4*)((char*)sK[0] + swz(row, ch)) = *(const uint4*)(Kb + row * D_K + ch * 8);
        *(uint4*)((char*)sV[0] + swz(row, ch)) = *(const uint4*)(Vb + row * D_K + ch * 8);
    }
    __syncthreads();

    // O accumulators [mt][ntd][4], softmax state per row [mt][r01]
    float o[2][8][4];
#pragma unroll
    for (int mt = 0; mt < 2; mt++)
#pragma unroll
        for (int n = 0; n < 8; n++)
#pragma unroll
            for (int c = 0; c < 4; c++) o[mt][n][c] = 0.0f;
    float mrow[2][2] = {{-1e30f, -1e30f}, {-1e30f, -1e30f}};
    float lrow[2][2] = {{0.0f, 0.0f}, {0.0f, 0.0f}};

    for (int kt = 0; kt < NTILES; kt++) {
        const int cur = kt & 1;
        const unsigned cK = cur ? bK1 : bK0;
        const unsigned cV = cur ? bV1 : bV0;

        // ---- Issue next tile's global loads early (latency hidden by MMA1) ----
        uint4 stK[4], stV[4];
        if (kt + 1 < NTILES) {
            const __half* Kp = Kb + (size_t)(kt + 1) * 64 * D_K;
            const __half* Vp = Vb + (size_t)(kt + 1) * 64 * D_K;
#pragma unroll
            for (int i = 0; i < 4; i++) {
                int g = tid + 128 * i;
                int row = g >> 3, ch = g & 7;
                stK[i] = *(const uint4*)(Kp + row * D_K + ch * 8);
                stV[i] = *(const uint4*)(Vp + row * D_K + ch * 8);
            }
        }

        // ---- MMA1: S = Q * K^T ----
        float s[2][8][4];
#pragma unroll
        for (int mt = 0; mt < 2; mt++)
#pragma unroll
            for (int n = 0; n < 8; n++)
#pragma unroll
                for (int c = 0; c < 4; c++) s[mt][n][c] = 0.0f;

#pragma unroll
        for (int kk = 0; kk < 4; kk++) {
            unsigned a[2][4];
#pragma unroll
            for (int mt = 0; mt < 2; mt++) {
                int row = 32 * w + 16 * mt + (lane & 15);
                int ch  = 2 * kk + (lane >> 4);
                ldm_x4(bQ + swz(row, ch), a[mt][0], a[mt][1], a[mt][2], a[mt][3]);
            }
#pragma unroll
            for (int nt2 = 0; nt2 < 4; nt2++) {
                unsigned b0, b1, b2, b3;
                int row = nt2 * 16 + ((lane >> 4) << 3) + (lane & 7);
                int ch  = 2 * kk + ((lane >> 3) & 1);
                ldm_x4(cK + swz(row, ch), b0, b1, b2, b3);
#pragma unroll
                for (int mt = 0; mt < 2; mt++) {
                    mma16816(s[mt][2 * nt2 + 0], a[mt], b0, b1);
                    mma16816(s[mt][2 * nt2 + 1], a[mt], b2, b3);
                }
            }
        }

        // ---- Stash next tile into the other buffer (no sync needed yet) ----
        if (kt + 1 < NTILES) {
            __half* nK = sK[1 - cur];
            __half* nV = sV[1 - cur];
#pragma unroll
            for (int i = 0; i < 4; i++) {
                int g = tid + 128 * i;
                int row = g >> 3, ch = g & 7;
                *(uint4*)((char*)nK + swz(row, ch)) = stK[i];
                *(uint4*)((char*)nV + swz(row, ch)) = stV[i];
            }
        }

        // ---- Online softmax (base-2; Q pre-scaled by 0.125*log2e) ----
        unsigned pa_lo[2][8], pa_hi[2][8];
#pragma unroll
        for (int mt = 0; mt < 2; mt++) {
            float mx0 = -1e30f, mx1 = -1e30f;
#pragma unroll
            for (int n = 0; n < 8; n++) {
                mx0 = fmaxf(mx0, fmaxf(s[mt][n][0], s[mt][n][1]));
                mx1 = fmaxf(mx1, fmaxf(s[mt][n][2], s[mt][n][3]));
            }
            mx0 = fmaxf(mx0, __shfl_xor_sync(0xffffffffu, mx0, 1));
            mx0 = fmaxf(mx0, __shfl_xor_sync(0xffffffffu, mx0, 2));
            mx1 = fmaxf(mx1, __shfl_xor_sync(0xffffffffu, mx1, 1));
            mx1 = fmaxf(mx1, __shfl_xor_sync(0xffffffffu, mx1, 2));

            float m0n = fmaxf(mrow[mt][0], mx0);
            float m1n = fmaxf(mrow[mt][1], mx1);
            float c0 = fast_exp2(mrow[mt][0] - m0n);
            float c1 = fast_exp2(mrow[mt][1] - m1n);
            mrow[mt][0] = m0n;
            mrow[mt][1] = m1n;

            float sum0 = 0.0f, sum1 = 0.0f;
#pragma unroll
            for (int n = 0; n < 8; n++) {
                float p0 = fast_exp2(s[mt][n][0] - m0n);
                float p1 = fast_exp2(s[mt][n][1] - m0n);
                float p2 = fast_exp2(s[mt][n][2] - m1n);
                float p3 = fast_exp2(s[mt][n][3] - m1n);
                sum0 += p0 + p1;
                sum1 += p2 + p3;
                __half2 lo = __floats2half2_rn(p0, p1);
                __half2 hi = __floats2half2_rn(p2, p3);
                pa_lo[mt][n] = *reinterpret_cast<unsigned*>(&lo);
                pa_hi[mt][n] = *reinterpret_cast<unsigned*>(&hi);
            }
            sum0 += __shfl_xor_sync(0xffffffffu, sum0, 1);
            sum0 += __shfl_xor_sync(0xffffffffu, sum0, 2);
            sum1 += __shfl_xor_sync(0xffffffffu, sum1, 1);
            sum1 += __shfl_xor_sync(0xffffffffu, sum1, 2);
            lrow[mt][0] = lrow[mt][0] * c0 + sum0;
            lrow[mt][1] = lrow[mt][1] * c1 + sum1;

#pragma unroll
            for (int n = 0; n < 8; n++) {
                o[mt][n][0] *= c0;
                o[mt][n][1] *= c0;
                o[mt][n][2] *= c1;
                o[mt][n][3] *= c1;
            }
        }

        // ---- MMA2: O += P * V ----
#pragma unroll
        for (int kk = 0; kk < 4; kk++) {
            unsigned aP[2][4];
#pragma unroll
            for (int mt = 0; mt < 2; mt++) {
                aP[mt][0] = pa_lo[mt][2 * kk];
                aP[mt][1] = pa_hi[mt][2 * kk];
                aP[mt][2] = pa_lo[mt][2 * kk + 1];
                aP[mt][3] = pa_hi[mt][2 * kk + 1];
            }
#pragma unroll
            for (int j2 = 0; j2 < 4; j2++) {
                unsigned b0, b1, b2, b3;
                int row = kk * 16 + (((lane >> 3) & 1) << 3) + (lane & 7);
                int ch  = 2 * j2 + (lane >> 4);
                ldm_x4_t(cV + swz(row, ch), b0, b1, b2, b3);
#pragma unroll
                for (int mt = 0; mt < 2; mt++) {
                    mma16816(o[mt][2 * j2 + 0], aP[mt], b0, b1);
                    mma16816(o[mt][2 * j2 + 1], aP[mt], b2, b3);
                }
            }
        }

        __syncthreads();   // done reading cur buffers & writing next buffers
    }

    // ---- Epilogue: normalize, write fp32 to g_o[(b*T + t)*512 + h*64 + d] ----
    const int b = bh >> 3;
    const int h = bh & 7;
#pragma unroll
    for (int mt = 0; mt < 2; mt++) {
#pragma unroll
        for (int r01 = 0; r01 < 2; r01++) {
            int t = qt * 128 + 32 * w + 16 * mt + gid + 8 * r01;
            float inv = 1.0f / lrow[mt][r01];
            float* op = &g_o[((size_t)(b * T_SEQ + t)) * D_MODEL + h * D_K];
#pragma unroll
            for (int n = 0; n < 8; n++) {
                float2 v;
                v.x = o[mt][n][2 * r01 + 0] * inv;
                v.y = o[mt][n][2 * r01 + 1] * inv;
                *(float2*)(op + n * 8 + 2 * tig) = v;
            }
        }
    }
}

// ===========================================================================
// Launch
// ===========================================================================
extern "C" void kernel_launch(void* const* d_in, const int* in_sizes, int n_in,
                              void* d_out, int out_size)
{
    const float* x  = (const float*)d_in[0];
    const float* Wq = (const float*)d_in[1];
    const float* bq = (const float*)d_in[2];
    const float* Wk = (const float*)d_in[3];
    const float* bk = (const float*)d_in[4];
    const float* Wv = (const float*)d_in[5];
    const float* bv = (const float*)d_in[6];
    const float* Wo = (const float*)d_in[7];
    const float* bo = (const float*)d_in[8];
    float* out = (float*)d_out;

    dim3 gproj(D_MODEL / 64, M_ROWS / 64, 1);   // (8, 128)
    dim3 blk(128, 1, 1);

    gemm_bias_kernel<<<gproj, blk>>>(x, Wq, bq, nullptr, 0);
    gemm_bias_kernel<<<gproj, blk>>>(x, Wk, bk, nullptr, 1);
    gemm_bias_kernel<<<gproj, blk>>>(x, Wv, bv, nullptr, 2);

    dim3 gattn(T_SEQ / 128, BH, 1);             // (32, 16)
    attn_mma_kernel<<<gattn, blk>>>();

    gemm_bias_kernel<<<gproj, blk>>>(nullptr, Wo, bo, out, 3);
}

// round 11
// speedup vs baseline: 10.8807x; 2.1626x over previous
#include <cuda_runtime.h>
#include <cuda_fp16.h>

// Problem constants
#define T_SEQ   4096
#define D_MODEL 512
#define N_HEADS 8
#define D_K     64
#define BATCH   2
#define BH      (BATCH * N_HEADS)       // 16
#define M_ROWS  (BATCH * T_SEQ)         // 8192
#define NTILES  (T_SEQ / 64)            // 64 key tiles

// Q is pre-scaled by 0.125 * log2(e) so softmax runs in base-2 domain.
#define QSCALE  (0.125f * 1.44269504088896f)

// f16 intermediates (16B aligned for uint4 access)
__device__ __align__(16) __half g_xh[(size_t)M_ROWS * D_MODEL];    // x f16
__device__ __align__(16) __half g_wq[(size_t)D_MODEL * D_MODEL];
__device__ __align__(16) __half g_wk[(size_t)D_MODEL * D_MODEL];
__device__ __align__(16) __half g_wv[(size_t)D_MODEL * D_MODEL];
__device__ __align__(16) __half g_wo[(size_t)D_MODEL * D_MODEL];
__device__ __align__(16) __half g_qh[(size_t)BH * T_SEQ * D_K];    // [bh][t][64] (pre-scaled)
__device__ __align__(16) __half g_kh[(size_t)BH * T_SEQ * D_K];
__device__ __align__(16) __half g_vh[(size_t)BH * T_SEQ * D_K];
__device__ __align__(16) __half g_oh[(size_t)M_ROWS * D_MODEL];    // attention out f16

// ===========================================================================
// Small helpers
// ===========================================================================
__device__ __forceinline__ unsigned smem_u32(const void* p) {
    unsigned a;
    asm("{ .reg .u64 t; cvta.to.shared.u64 t, %1; cvt.u32.u64 %0, t; }" : "=r"(a) : "l"(p));
    return a;
}
__device__ __forceinline__ float fast_exp2(float x) {
    float y;
    asm("ex2.approx.ftz.f32 %0, %1;" : "=f"(y) : "f"(x));
    return y;
}
// Row-major [row][64 halfs] tile with XOR swizzle on 16B chunks:
// byte offset of (row, chunk) = row*128 + (chunk ^ (row&7))*16
__device__ __forceinline__ unsigned swz(int row, int ch) {
    return (unsigned)(row * 128 + ((ch ^ (row & 7)) << 4));
}
__device__ __forceinline__ void ldm_x4(unsigned addr, unsigned& r0, unsigned& r1,
                                       unsigned& r2, unsigned& r3) {
    asm volatile("ldmatrix.sync.aligned.m8n8.x4.shared.b16 {%0,%1,%2,%3}, [%4];"
                 : "=r"(r0), "=r"(r1), "=r"(r2), "=r"(r3) : "r"(addr));
}
__device__ __forceinline__ void ldm_x4_t(unsigned addr, unsigned& r0, unsigned& r1,
                                         unsigned& r2, unsigned& r3) {
    asm volatile("ldmatrix.sync.aligned.m8n8.x4.trans.shared.b16 {%0,%1,%2,%3}, [%4];"
                 : "=r"(r0), "=r"(r1), "=r"(r2), "=r"(r3) : "r"(addr));
}
__device__ __forceinline__ void mma16816(float* c, const unsigned* a,
                                         unsigned b0, unsigned b1) {
    asm volatile(
        "mma.sync.aligned.m16n8k16.row.col.f32.f16.f16.f32 "
        "{%0,%1,%2,%3}, {%4,%5,%6,%7}, {%8,%9}, {%0,%1,%2,%3};"
        : "+f"(c[0]), "+f"(c[1]), "+f"(c[2]), "+f"(c[3])
        : "r"(a[0]), "r"(a[1]), "r"(a[2]), "r"(a[3]), "r"(b0), "r"(b1));
}

// ===========================================================================
// fp32 -> f16 convert. dst selected by mode: 0=x, 1=Wq, 2=Wk, 3=Wv, 4=Wo.
// i-th float4 (src elems [4i,4i+4)) -> dst halfs [4i,4i+4) (uint2, 8 bytes).
// ===========================================================================
__global__ __launch_bounds__(256)
void f2h_kernel(const float* __restrict__ src, int n4, int mode)
{
    __half* dst = (mode == 0) ? g_xh : (mode == 1) ? g_wq :
                  (mode == 2) ? g_wk : (mode == 3) ? g_wv : g_wo;
    for (int i = blockIdx.x * blockDim.x + threadIdx.x; i < n4;
         i += gridDim.x * blockDim.x) {
        float4 v = *(const float4*)(src + 4 * (size_t)i);
        __half2 lo = __floats2half2_rn(v.x, v.y);
        __half2 hi = __floats2half2_rn(v.z, v.w);
        uint2 pk;
        pk.x = *reinterpret_cast<unsigned*>(&lo);
        pk.y = *reinterpret_cast<unsigned*>(&hi);
        *(uint2*)(dst + 4 * (size_t)i) = pk;   // FIXED: was dst + 8*i (OOB + gaps)
    }
}

// ===========================================================================
// f16 tensor-core projection GEMM: C[m,n] = sum_k A[m,k]*W[n,k] + bias[n]
// A row-major f16 (k contiguous), W row-major f16 [n][k].
// CTA tile 128m x 64n, K-chunks of 64, 4 warps (warp w = rows 32w..32w+31).
// mode 0: -> g_qh [bh][t][64] * QSCALE   (blockIdx.x == head)
// mode 1: -> g_kh    mode 2: -> g_vh
// mode 3: -> outf fp32 [m][512]  (A = g_oh)
// ===========================================================================
__global__ __launch_bounds__(128)
void gemm_h_kernel(const float* __restrict__ bias, float* __restrict__ outf, int mode)
{
    __shared__ __half sA[2][128 * 64];   // 2 x 16 KB
    __shared__ __half sB[2][64 * 64];    // 2 x 8 KB  (total 48 KB)

    const __half* A = (mode <= 2) ? g_xh : g_oh;
    const __half* W = (mode == 0) ? g_wq : (mode == 1) ? g_wk :
                      (mode == 2) ? g_wv : g_wo;

    const int tid  = threadIdx.x;
    const int w    = tid >> 5;
    const int lane = tid & 31;
    const int gid  = lane >> 2;
    const int tig  = lane & 3;
    const int n0   = blockIdx.x * 64;
    const int m0   = blockIdx.y * 128;

    const unsigned bA0 = smem_u32(sA[0]), bA1 = smem_u32(sA[1]);
    const unsigned bB0 = smem_u32(sB[0]), bB1 = smem_u32(sB[1]);

    const int arow = tid >> 3, ach = tid & 7;   // loader: rows arow+16i, chunk ach

    // ---- chunk 0 direct load ----
#pragma unroll
    for (int i = 0; i < 8; i++) {
        int row = arow + 16 * i;
        *(uint4*)((char*)sA[0] + swz(row, ach)) =
            *(const uint4*)(A + (size_t)(m0 + row) * D_MODEL + ach * 8);
    }
#pragma unroll
    for (int i = 0; i < 4; i++) {
        int row = arow + 16 * i;
        *(uint4*)((char*)sB[0] + swz(row, ach)) =
            *(const uint4*)(W + (size_t)(n0 + row) * D_MODEL + ach * 8);
    }
    __syncthreads();

    float c[2][8][4];
#pragma unroll
    for (int mt = 0; mt < 2; mt++)
#pragma unroll
        for (int n = 0; n < 8; n++)
#pragma unroll
            for (int cc = 0; cc < 4; cc++) c[mt][n][cc] = 0.0f;

    for (int kt = 0; kt < D_MODEL / 64; kt++) {
        const int cur = kt & 1;
        const unsigned cA = cur ? bA1 : bA0;
        const unsigned cB = cur ? bB1 : bB0;

        // prefetch next chunk to regs (FULL tiles: 8 uint4 A, 4 uint4 B)
        uint4 pA[8], pB[4];
        if (kt + 1 < D_MODEL / 64) {
            const __half* Ap = A + (size_t)(kt + 1) * 64;
            const __half* Wp = W + (size_t)(kt + 1) * 64;
#pragma unroll
            for (int i = 0; i < 8; i++) {
                int row = arow + 16 * i;
                pA[i] = *(const uint4*)(Ap + (size_t)(m0 + row) * D_MODEL + ach * 8);
            }
#pragma unroll
            for (int i = 0; i < 4; i++) {
                int row = arow + 16 * i;
                pB[i] = *(const uint4*)(Wp + (size_t)(n0 + row) * D_MODEL + ach * 8);
            }
        }

        // MMA over this chunk
#pragma unroll
        for (int kk = 0; kk < 4; kk++) {
            unsigned a[2][4];
#pragma unroll
            for (int mt = 0; mt < 2; mt++) {
                int row = 32 * w + 16 * mt + (lane & 15);
                int ch  = 2 * kk + (lane >> 4);
                ldm_x4(cA + swz(row, ch), a[mt][0], a[mt][1], a[mt][2], a[mt][3]);
            }
#pragma unroll
            for (int nt2 = 0; nt2 < 4; nt2++) {
                unsigned b0, b1, b2, b3;
                int row = nt2 * 16 + ((lane >> 4) << 3) + (lane & 7);
                int ch  = 2 * kk + ((lane >> 3) & 1);
                ldm_x4(cB + swz(row, ch), b0, b1, b2, b3);
#pragma unroll
                for (int mt = 0; mt < 2; mt++) {
                    mma16816(c[mt][2 * nt2 + 0], a[mt], b0, b1);
                    mma16816(c[mt][2 * nt2 + 1], a[mt], b2, b3);
                }
            }
        }

        // store prefetched chunk
        if (kt + 1 < D_MODEL / 64) {
            __half* nA = (__half*)(cur ? (void*)sA[0] : (void*)sA[1]);
            __half* nB = (__half*)(cur ? (void*)sB[0] : (void*)sB[1]);
#pragma unroll
            for (int i = 0; i < 8; i++)
                *(uint4*)((char*)nA + swz(arow + 16 * i, ach)) = pA[i];
#pragma unroll
            for (int i = 0; i < 4; i++)
                *(uint4*)((char*)nB + swz(arow + 16 * i, ach)) = pB[i];
        }
        __syncthreads();
    }

    // ---- Epilogue ----
    if (mode <= 2) {
        __half* dst = (mode == 0) ? g_qh : (mode == 1) ? g_kh : g_vh;
        const float sc = (mode == 0) ? QSCALE : 1.0f;
        const int h = blockIdx.x;
#pragma unroll
        for (int mt = 0; mt < 2; mt++)
#pragma unroll
            for (int r01 = 0; r01 < 2; r01++) {
                int m = m0 + 32 * w + 16 * mt + gid + 8 * r01;
                int b = m >> 12;
                int t = m & (T_SEQ - 1);
                __half* op = &dst[(((size_t)(b * N_HEADS + h)) * T_SEQ + t) * D_K];
#pragma unroll
                for (int n = 0; n < 8; n++) {
                    int d = n * 8 + 2 * tig;
                    __half2 hv = __floats2half2_rn(
                        (c[mt][n][2 * r01 + 0] + bias[n0 + d]) * sc,
                        (c[mt][n][2 * r01 + 1] + bias[n0 + d + 1]) * sc);
                    *(__half2*)(op + d) = hv;
                }
            }
    } else {
#pragma unroll
        for (int mt = 0; mt < 2; mt++)
#pragma unroll
            for (int r01 = 0; r01 < 2; r01++) {
                int m = m0 + 32 * w + 16 * mt + gid + 8 * r01;
                float* op = &outf[(size_t)m * D_MODEL + n0];
#pragma unroll
                for (int n = 0; n < 8; n++) {
                    int d = n * 8 + 2 * tig;
                    float2 v;
                    v.x = c[mt][n][2 * r01 + 0] + bias[n0 + d];
                    v.y = c[mt][n][2 * r01 + 1] + bias[n0 + d + 1];
                    *(float2*)(op + d) = v;
                }
            }
    }
}

// ===========================================================================
// mma.sync f16 flash attention (validated in R5; epilogue writes f16 g_oh).
// ===========================================================================
__global__ __launch_bounds__(128)
void attn_mma_kernel()
{
    __shared__ __half sQ[128 * 64];        // 16 KB
    __shared__ __half sK[2][64 * 64];      // 16 KB
    __shared__ __half sV[2][64 * 64];      // 16 KB   (total 48 KB)

    const int tid  = threadIdx.x;
    const int w    = tid >> 5;
    const int lane = tid & 31;
    const int gid  = lane >> 2;
    const int tig  = lane & 3;
    const int bh   = blockIdx.y;
    const int qt   = blockIdx.x;

    const __half* Qp = g_qh + (size_t)bh * T_SEQ * D_K + (size_t)qt * 128 * D_K;
    const __half* Kb = g_kh + (size_t)bh * T_SEQ * D_K;
    const __half* Vb = g_vh + (size_t)bh * T_SEQ * D_K;

    const unsigned bQ = smem_u32(sQ);
    const unsigned bK0 = smem_u32(sK[0]), bK1 = smem_u32(sK[1]);
    const unsigned bV0 = smem_u32(sV[0]), bV1 = smem_u32(sV[1]);

#pragma unroll
    for (int i = 0; i < 8; i++) {
        int g = tid + 128 * i;
        int row = g >> 3, ch = g & 7;
        uint4 v = *(const uint4*)(Qp + row * D_K + ch * 8);
        *(uint4*)((char*)sQ + swz(row, ch)) = v;
    }
#pragma unroll
    for (int i = 0; i < 4; i++) {
        int g = tid + 128 * i;
        int row = g >> 3, ch = g & 7;
        *(uint4*)((char*)sK[0] + swz(row, ch)) = *(const uint4*)(Kb + row * D_K + ch * 8);
        *(uint4*)((char*)sV[0] + swz(row, ch)) = *(const uint4*)(Vb + row * D_K + ch * 8);
    }
    __syncthreads();

    float o[2][8][4];
#pragma unroll
    for (int mt = 0; mt < 2; mt++)
#pragma unroll
        for (int n = 0; n < 8; n++)
#pragma unroll
            for (int cc = 0; cc < 4; cc++) o[mt][n][cc] = 0.0f;
    float mrow[2][2] = {{-1e30f, -1e30f}, {-1e30f, -1e30f}};
    float lrow[2][2] = {{0.0f, 0.0f}, {0.0f, 0.0f}};

    for (int kt = 0; kt < NTILES; kt++) {
        const int cur = kt & 1;
        const unsigned cK = cur ? bK1 : bK0;
        const unsigned cV = cur ? bV1 : bV0;

        uint4 stK[4], stV[4];
        if (kt + 1 < NTILES) {
            const __half* Kp = Kb + (size_t)(kt + 1) * 64 * D_K;
            const __half* Vp = Vb + (size_t)(kt + 1) * 64 * D_K;
#pragma unroll
            for (int i = 0; i < 4; i++) {
                int g = tid + 128 * i;
                int row = g >> 3, ch = g & 7;
                stK[i] = *(const uint4*)(Kp + row * D_K + ch * 8);
                stV[i] = *(const uint4*)(Vp + row * D_K + ch * 8);
            }
        }

        float s[2][8][4];
#pragma unroll
        for (int mt = 0; mt < 2; mt++)
#pragma unroll
            for (int n = 0; n < 8; n++)
#pragma unroll
                for (int cc = 0; cc < 4; cc++) s[mt][n][cc] = 0.0f;

#pragma unroll
        for (int kk = 0; kk < 4; kk++) {
            unsigned a[2][4];
#pragma unroll
            for (int mt = 0; mt < 2; mt++) {
                int row = 32 * w + 16 * mt + (lane & 15);
                int ch  = 2 * kk + (lane >> 4);
                ldm_x4(bQ + swz(row, ch), a[mt][0], a[mt][1], a[mt][2], a[mt][3]);
            }
#pragma unroll
            for (int nt2 = 0; nt2 < 4; nt2++) {
                unsigned b0, b1, b2, b3;
                int row = nt2 * 16 + ((lane >> 4) << 3) + (lane & 7);
                int ch  = 2 * kk + ((lane >> 3) & 1);
                ldm_x4(cK + swz(row, ch), b0, b1, b2, b3);
#pragma unroll
                for (int mt = 0; mt < 2; mt++) {
                    mma16816(s[mt][2 * nt2 + 0], a[mt], b0, b1);
                    mma16816(s[mt][2 * nt2 + 1], a[mt], b2, b3);
                }
            }
        }

        if (kt + 1 < NTILES) {
            __half* nK = sK[1 - cur];
            __half* nV = sV[1 - cur];
#pragma unroll
            for (int i = 0; i < 4; i++) {
                int g = tid + 128 * i;
                int row = g >> 3, ch = g & 7;
                *(uint4*)((char*)nK + swz(row, ch)) = stK[i];
                *(uint4*)((char*)nV + swz(row, ch)) = stV[i];
            }
        }

        unsigned pa_lo[2][8], pa_hi[2][8];
#pragma unroll
        for (int mt = 0; mt < 2; mt++) {
            float mx0 = -1e30f, mx1 = -1e30f;
#pragma unroll
            for (int n = 0; n < 8; n++) {
                mx0 = fmaxf(mx0, fmaxf(s[mt][n][0], s[mt][n][1]));
                mx1 = fmaxf(mx1, fmaxf(s[mt][n][2], s[mt][n][3]));
            }
            mx0 = fmaxf(mx0, __shfl_xor_sync(0xffffffffu, mx0, 1));
            mx0 = fmaxf(mx0, __shfl_xor_sync(0xffffffffu, mx0, 2));
            mx1 = fmaxf(mx1, __shfl_xor_sync(0xffffffffu, mx1, 1));
            mx1 = fmaxf(mx1, __shfl_xor_sync(0xffffffffu, mx1, 2));

            float m0n = fmaxf(mrow[mt][0], mx0);
            float m1n = fmaxf(mrow[mt][1], mx1);
            float c0 = fast_exp2(mrow[mt][0] - m0n);
            float c1 = fast_exp2(mrow[mt][1] - m1n);
            mrow[mt][0] = m0n;
            mrow[mt][1] = m1n;

            float sum0 = 0.0f, sum1 = 0.0f;
#pragma unroll
            for (int n = 0; n < 8; n++) {
                float p0 = fast_exp2(s[mt][n][0] - m0n);
                float p1 = fast_exp2(s[mt][n][1] - m0n);
                float p2 = fast_exp2(s[mt][n][2] - m1n);
                float p3 = fast_exp2(s[mt][n][3] - m1n);
                sum0 += p0 + p1;
                sum1 += p2 + p3;
                __half2 lo = __floats2half2_rn(p0, p1);
                __half2 hi = __floats2half2_rn(p2, p3);
                pa_lo[mt][n] = *reinterpret_cast<unsigned*>(&lo);
                pa_hi[mt][n] = *reinterpret_cast<unsigned*>(&hi);
            }
            sum0 += __shfl_xor_sync(0xffffffffu, sum0, 1);
            sum0 += __shfl_xor_sync(0xffffffffu, sum0, 2);
            sum1 += __shfl_xor_sync(0xffffffffu, sum1, 1);
            sum1 += __shfl_xor_sync(0xffffffffu, sum1, 2);
            lrow[mt][0] = lrow[mt][0] * c0 + sum0;
            lrow[mt][1] = lrow[mt][1] * c1 + sum1;

#pragma unroll
            for (int n = 0; n < 8; n++) {
                o[mt][n][0] *= c0;
                o[mt][n][1] *= c0;
                o[mt][n][2] *= c1;
                o[mt][n][3] *= c1;
            }
        }

#pragma unroll
        for (int kk = 0; kk < 4; kk++) {
            unsigned aP[2][4];
#pragma unroll
            for (int mt = 0; mt < 2; mt++) {
                aP[mt][0] = pa_lo[mt][2 * kk];
                aP[mt][1] = pa_hi[mt][2 * kk];
                aP[mt][2] = pa_lo[mt][2 * kk + 1];
                aP[mt][3] = pa_hi[mt][2 * kk + 1];
            }
#pragma unroll
            for (int j2 = 0; j2 < 4; j2++) {
                unsigned b0, b1, b2, b3;
                int row = kk * 16 + (((lane >> 3) & 1) << 3) + (lane & 7);
                int ch  = 2 * j2 + (lane >> 4);
                ldm_x4_t(cV + swz(row, ch), b0, b1, b2, b3);
#pragma unroll
                for (int mt = 0; mt < 2; mt++) {
                    mma16816(o[mt][2 * j2 + 0], aP[mt], b0, b1);
                    mma16816(o[mt][2 * j2 + 1], aP[mt], b2, b3);
                }
            }
        }

        __syncthreads();
    }

    // ---- Epilogue: normalize, write f16 to g_oh[(b*T + t)*512 + h*64 + d] ----
    const int b = bh >> 3;
    const int h = bh & 7;
#pragma unroll
    for (int mt = 0; mt < 2; mt++) {
#pragma unroll
        for (int r01 = 0; r01 < 2; r01++) {
            int t = qt * 128 + 32 * w + 16 * mt + gid + 8 * r01;
            float inv = 1.0f / lrow[mt][r01];
            __half* op = &g_oh[((size_t)(b * T_SEQ + t)) * D_MODEL + h * D_K];
#pragma unroll
            for (int n = 0; n < 8; n++) {
                __half2 hv = __floats2half2_rn(o[mt][n][2 * r01 + 0] * inv,
                                               o[mt][n][2 * r01 + 1] * inv);
                *(__half2*)(op + n * 8 + 2 * tig) = hv;
            }
        }
    }
}

// ===========================================================================
// Launch
// ===========================================================================
extern "C" void kernel_launch(void* const* d_in, const int* in_sizes, int n_in,
                              void* d_out, int out_size)
{
    const float* x  = (const float*)d_in[0];
    const float* Wq = (const float*)d_in[1];
    const float* bq = (const float*)d_in[2];
    const float* Wk = (const float*)d_in[3];
    const float* bk = (const float*)d_in[4];
    const float* Wv = (const float*)d_in[5];
    const float* bv = (const float*)d_in[6];
    const float* Wo = (const float*)d_in[7];
    const float* bo = (const float*)d_in[8];
    float* out = (float*)d_out;

    // fp32 -> f16 converts
    f2h_kernel<<<512, 256>>>(x,  (M_ROWS * D_MODEL) / 4, 0);
    f2h_kernel<<<128, 256>>>(Wq, (D_MODEL * D_MODEL) / 4, 1);
    f2h_kernel<<<128, 256>>>(Wk, (D_MODEL * D_MODEL) / 4, 2);
    f2h_kernel<<<128, 256>>>(Wv, (D_MODEL * D_MODEL) / 4, 3);
    f2h_kernel<<<128, 256>>>(Wo, (D_MODEL * D_MODEL) / 4, 4);

    dim3 gproj(D_MODEL / 64, M_ROWS / 128, 1);  // (8, 64)
    dim3 blk(128, 1, 1);

    gemm_h_kernel<<<gproj, blk>>>(bq, nullptr, 0);
    gemm_h_kernel<<<gproj, blk>>>(bk, nullptr, 1);
    gemm_h_kernel<<<gproj, blk>>>(bv, nullptr, 2);

    dim3 gattn(T_SEQ / 128, BH, 1);             // (32, 16)
    attn_mma_kernel<<<gattn, blk>>>();

    gemm_h_kernel<<<gproj, blk>>>(bo, out, 3);
}

// round 13
// speedup vs baseline: 11.9624x; 1.0994x over previous
#include <cuda_runtime.h>
#include <cuda_fp16.h>

// Problem constants
#define T_SEQ   4096
#define D_MODEL 512
#define N_HEADS 8
#define D_K     64
#define BATCH   2
#define BH      (BATCH * N_HEADS)       // 16
#define M_ROWS  (BATCH * T_SEQ)         // 8192
#define NTILES  (T_SEQ / 64)            // 64 key tiles

// Q is pre-scaled by 0.125 * log2(e) so softmax runs in base-2 domain.
#define QSCALE  (0.125f * 1.44269504088896f)

// f16 intermediates (16B aligned for uint4 access)
__device__ __align__(16) __half g_xh[(size_t)M_ROWS * D_MODEL];    // x f16
__device__ __align__(16) __half g_wq[(size_t)D_MODEL * D_MODEL];
__device__ __align__(16) __half g_wk[(size_t)D_MODEL * D_MODEL];
__device__ __align__(16) __half g_wv[(size_t)D_MODEL * D_MODEL];
__device__ __align__(16) __half g_wo[(size_t)D_MODEL * D_MODEL];
__device__ __align__(16) __half g_qh[(size_t)BH * T_SEQ * D_K];    // [bh][t][64] (pre-scaled)
__device__ __align__(16) __half g_kh[(size_t)BH * T_SEQ * D_K];
__device__ __align__(16) __half g_vh[(size_t)BH * T_SEQ * D_K];
__device__ __align__(16) __half g_oh[(size_t)M_ROWS * D_MODEL];    // attention out f16

// ===========================================================================
// Small helpers
// ===========================================================================
__device__ __forceinline__ unsigned smem_u32(const void* p) {
    unsigned a;
    asm("{ .reg .u64 t; cvta.to.shared.u64 t, %1; cvt.u32.u64 %0, t; }" : "=r"(a) : "l"(p));
    return a;
}
__device__ __forceinline__ float fast_exp2(float x) {
    float y;
    asm("ex2.approx.ftz.f32 %0, %1;" : "=f"(y) : "f"(x));
    return y;
}
// Row-major [row][64 halfs] tile with XOR swizzle on 16B chunks:
// byte offset of (row, chunk) = row*128 + (chunk ^ (row&7))*16
__device__ __forceinline__ unsigned swz(int row, int ch) {
    return (unsigned)(row * 128 + ((ch ^ (row & 7)) << 4));
}
__device__ __forceinline__ void ldm_x4(unsigned addr, unsigned& r0, unsigned& r1,
                                       unsigned& r2, unsigned& r3) {
    asm volatile("ldmatrix.sync.aligned.m8n8.x4.shared.b16 {%0,%1,%2,%3}, [%4];"
                 : "=r"(r0), "=r"(r1), "=r"(r2), "=r"(r3) : "r"(addr));
}
__device__ __forceinline__ void ldm_x4_t(unsigned addr, unsigned& r0, unsigned& r1,
                                         unsigned& r2, unsigned& r3) {
    asm volatile("ldmatrix.sync.aligned.m8n8.x4.trans.shared.b16 {%0,%1,%2,%3}, [%4];"
                 : "=r"(r0), "=r"(r1), "=r"(r2), "=r"(r3) : "r"(addr));
}
__device__ __forceinline__ void mma16816(float* c, const unsigned* a,
                                         unsigned b0, unsigned b1) {
    asm volatile(
        "mma.sync.aligned.m16n8k16.row.col.f32.f16.f16.f32 "
        "{%0,%1,%2,%3}, {%4,%5,%6,%7}, {%8,%9}, {%0,%1,%2,%3};"
        : "+f"(c[0]), "+f"(c[1]), "+f"(c[2]), "+f"(c[3])
        : "r"(a[0]), "r"(a[1]), "r"(a[2]), "r"(a[3]), "r"(b0), "r"(b1));
}
__device__ __forceinline__ void cp_async16(unsigned dst, const void* src) {
    asm volatile("cp.async.cg.shared.global [%0], [%1], 16;" :: "r"(dst), "l"(src));
}
#define CP_COMMIT()  asm volatile("cp.async.commit_group;" ::: "memory")
#define CP_WAIT(n)   asm volatile("cp.async.wait_group %0;" :: "n"(n) : "memory")

// ===========================================================================
// fp32 -> f16 converts.
// ===========================================================================
__global__ __launch_bounds__(256)
void f2h_x_kernel(const float* __restrict__ src, int n4)
{
    for (int i = blockIdx.x * blockDim.x + threadIdx.x; i < n4;
         i += gridDim.x * blockDim.x) {
        float4 v = *(const float4*)(src + 4 * (size_t)i);
        __half2 lo = __floats2half2_rn(v.x, v.y);
        __half2 hi = __floats2half2_rn(v.z, v.w);
        uint2 pk;
        pk.x = *reinterpret_cast<unsigned*>(&lo);
        pk.y = *reinterpret_cast<unsigned*>(&hi);
        *(uint2*)(g_xh + 4 * (size_t)i) = pk;
    }
}
// All four weight matrices in one launch: blockIdx.y selects.
__global__ __launch_bounds__(256)
void f2h_w_kernel(const float* __restrict__ wq, const float* __restrict__ wk,
                  const float* __restrict__ wv, const float* __restrict__ wo)
{
    const int sel = blockIdx.y;
    const float* src = (sel == 0) ? wq : (sel == 1) ? wk : (sel == 2) ? wv : wo;
    __half* dst = (sel == 0) ? g_wq : (sel == 1) ? g_wk : (sel == 2) ? g_wv : g_wo;
    const int n4 = (D_MODEL * D_MODEL) / 4;
    for (int i = blockIdx.x * blockDim.x + threadIdx.x; i < n4;
         i += gridDim.x * blockDim.x) {
        float4 v = *(const float4*)(src + 4 * (size_t)i);
        __half2 lo = __floats2half2_rn(v.x, v.y);
        __half2 hi = __floats2half2_rn(v.z, v.w);
        uint2 pk;
        pk.x = *reinterpret_cast<unsigned*>(&lo);
        pk.y = *reinterpret_cast<unsigned*>(&hi);
        *(uint2*)(dst + 4 * (size_t)i) = pk;
    }
}

// ===========================================================================
// f16 tensor-core GEMM body: C[m,n] = sum_k A[m,k]*W[n,k], fp32 accum.
// CTA tile 128m x 64n, K-chunks of 64, 4 warps. Returns accumulators.
// ===========================================================================
__device__ __forceinline__ void gemm_body(const __half* __restrict__ A,
                                          const __half* __restrict__ W,
                                          int m0, int n0,
                                          __half (*sA)[128 * 64], __half (*sB)[64 * 64],
                                          float c[2][8][4])
{
    const int tid  = threadIdx.x;
    const int w    = tid >> 5;
    const int lane = tid & 31;
    const unsigned bA0 = smem_u32(sA[0]), bA1 = smem_u32(sA[1]);
    const unsigned bB0 = smem_u32(sB[0]), bB1 = smem_u32(sB[1]);
    const int arow = tid >> 3, ach = tid & 7;

    // chunk 0 direct load
#pragma unroll
    for (int i = 0; i < 8; i++) {
        int row = arow + 16 * i;
        *(uint4*)((char*)sA[0] + swz(row, ach)) =
            *(const uint4*)(A + (size_t)(m0 + row) * D_MODEL + ach * 8);
    }
#pragma unroll
    for (int i = 0; i < 4; i++) {
        int row = arow + 16 * i;
        *(uint4*)((char*)sB[0] + swz(row, ach)) =
            *(const uint4*)(W + (size_t)(n0 + row) * D_MODEL + ach * 8);
    }
    __syncthreads();

#pragma unroll
    for (int mt = 0; mt < 2; mt++)
#pragma unroll
        for (int n = 0; n < 8; n++)
#pragma unroll
            for (int cc = 0; cc < 4; cc++) c[mt][n][cc] = 0.0f;

    for (int kt = 0; kt < D_MODEL / 64; kt++) {
        const int cur = kt & 1;
        const unsigned cA = cur ? bA1 : bA0;
        const unsigned cB = cur ? bB1 : bB0;

        uint4 pA[8], pB[4];
        if (kt + 1 < D_MODEL / 64) {
            const __half* Ap = A + (size_t)(kt + 1) * 64;
            const __half* Wp = W + (size_t)(kt + 1) * 64;
#pragma unroll
            for (int i = 0; i < 8; i++) {
                int row = arow + 16 * i;
                pA[i] = *(const uint4*)(Ap + (size_t)(m0 + row) * D_MODEL + ach * 8);
            }
#pragma unroll
            for (int i = 0; i < 4; i++) {
                int row = arow + 16 * i;
                pB[i] = *(const uint4*)(Wp + (size_t)(n0 + row) * D_MODEL + ach * 8);
            }
        }

#pragma unroll
        for (int kk = 0; kk < 4; kk++) {
            unsigned a[2][4];
#pragma unroll
            for (int mt = 0; mt < 2; mt++) {
                int row = 32 * w + 16 * mt + (lane & 15);
                int ch  = 2 * kk + (lane >> 4);
                ldm_x4(cA + swz(row, ch), a[mt][0], a[mt][1], a[mt][2], a[mt][3]);
            }
#pragma unroll
            for (int nt2 = 0; nt2 < 4; nt2++) {
                unsigned b0, b1, b2, b3;
                int row = nt2 * 16 + ((lane >> 4) << 3) + (lane & 7);
                int ch  = 2 * kk + ((lane >> 3) & 1);
                ldm_x4(cB + swz(row, ch), b0, b1, b2, b3);
#pragma unroll
                for (int mt = 0; mt < 2; mt++) {
                    mma16816(c[mt][2 * nt2 + 0], a[mt], b0, b1);
                    mma16816(c[mt][2 * nt2 + 1], a[mt], b2, b3);
                }
            }
        }

        if (kt + 1 < D_MODEL / 64) {
            __half* nA = (__half*)(cur ? (void*)sA[0] : (void*)sA[1]);
            __half* nB = (__half*)(cur ? (void*)sB[0] : (void*)sB[1]);
#pragma unroll
            for (int i = 0; i < 8; i++)
                *(uint4*)((char*)nA + swz(arow + 16 * i, ach)) = pA[i];
#pragma unroll
            for (int i = 0; i < 4; i++)
                *(uint4*)((char*)nB + swz(arow + 16 * i, ach)) = pB[i];
        }
        __syncthreads();
    }
}

// QKV projections fused: blockIdx.z = 0(Q)/1(K)/2(V).
__global__ __launch_bounds__(128)
void gemm_qkv_kernel(const float* __restrict__ bq, const float* __restrict__ bk,
                     const float* __restrict__ bv)
{
    __shared__ __half sA[2][128 * 64];
    __shared__ __half sB[2][64 * 64];

    const int z = blockIdx.z;
    const __half* W = (z == 0) ? g_wq : (z == 1) ? g_wk : g_wv;
    const float* bias = (z == 0) ? bq : (z == 1) ? bk : bv;
    __half* dst = (z == 0) ? g_qh : (z == 1) ? g_kh : g_vh;
    const float sc = (z == 0) ? QSCALE : 1.0f;

    const int n0 = blockIdx.x * 64;
    const int m0 = blockIdx.y * 128;
    const int h  = blockIdx.x;

    float c[2][8][4];
    gemm_body(g_xh, W, m0, n0, sA, sB, c);

    const int tid = threadIdx.x;
    const int w = tid >> 5, lane = tid & 31;
    const int gid = lane >> 2, tig = lane & 3;
#pragma unroll
    for (int mt = 0; mt < 2; mt++)
#pragma unroll
        for (int r01 = 0; r01 < 2; r01++) {
            int m = m0 + 32 * w + 16 * mt + gid + 8 * r01;
            int b = m >> 12;
            int t = m & (T_SEQ - 1);
            __half* op = &dst[(((size_t)(b * N_HEADS + h)) * T_SEQ + t) * D_K];
#pragma unroll
            for (int n = 0; n < 8; n++) {
                int d = n * 8 + 2 * tig;
                __half2 hv = __floats2half2_rn(
                    (c[mt][n][2 * r01 + 0] + bias[n0 + d]) * sc,
                    (c[mt][n][2 * r01 + 1] + bias[n0 + d + 1]) * sc);
                *(__half2*)(op + d) = hv;
            }
        }
}

// Output projection: A = g_oh, fp32 result to out.
__global__ __launch_bounds__(128)
void gemm_o_kernel(const float* __restrict__ bias, float* __restrict__ outf)
{
    __shared__ __half sA[2][128 * 64];
    __shared__ __half sB[2][64 * 64];

    const int n0 = blockIdx.x * 64;
    const int m0 = blockIdx.y * 128;

    float c[2][8][4];
    gemm_body(g_oh, g_wo, m0, n0, sA, sB, c);

    const int tid = threadIdx.x;
    const int w = tid >> 5, lane = tid & 31;
    const int gid = lane >> 2, tig = lane & 3;
#pragma unroll
    for (int mt = 0; mt < 2; mt++)
#pragma unroll
        for (int r01 = 0; r01 < 2; r01++) {
            int m = m0 + 32 * w + 16 * mt + gid + 8 * r01;
            float* op = &outf[(size_t)m * D_MODEL + n0];
#pragma unroll
            for (int n = 0; n < 8; n++) {
                int d = n * 8 + 2 * tig;
                float2 v;
                v.x = c[mt][n][2 * r01 + 0] + bias[n0 + d];
                v.y = c[mt][n][2 * r01 + 1] + bias[n0 + d + 1];
                *(float2*)(op + d) = v;
            }
        }
}

// ===========================================================================
// mma.sync f16 flash attention, v2:
//  - Q A-fragments hoisted to registers once (no per-tile Q ldmatrix)
//  - cp.async 3-stage K/V pipeline (prefetch depth 2, no register staging)
// smem: 3 stages x (K 8KB + V 8KB) = 48KB. Q staged through stage 2's region.
// ===========================================================================
__global__ __launch_bounds__(128)
void attn_mma_kernel()
{
    __shared__ __half sKV[3][2][64 * 64];   // [stage][0=K,1=V][8KB]

    const int tid  = threadIdx.x;
    const int w    = tid >> 5;
    const int lane = tid & 31;
    const int gid  = lane >> 2;
    const int tig  = lane & 3;
    const int bh   = blockIdx.y;
    const int qt   = blockIdx.x;

    const __half* Qp = g_qh + (size_t)bh * T_SEQ * D_K + (size_t)qt * 128 * D_K;
    const __half* Kb = g_kh + (size_t)bh * T_SEQ * D_K;
    const __half* Vb = g_vh + (size_t)bh * T_SEQ * D_K;

    unsigned uK[3], uV[3];
#pragma unroll
    for (int st = 0; st < 3; st++) {
        uK[st] = smem_u32(sKV[st][0]);
        uV[st] = smem_u32(sKV[st][1]);
    }
    const int arow = tid >> 3, ach = tid & 7;

    // ---- Prologue: Q through stage-2 smem -> register A-fragments ----
    {
        char* q2 = (char*)sKV[2];   // 16 KB region, rows 0..127 x 128B
#pragma unroll
        for (int i = 0; i < 8; i++) {
            int row = arow + 16 * i;
            *(uint4*)(q2 + swz(row, ach)) =
                *(const uint4*)(Qp + row * D_K + ach * 8);
        }
    }
    __syncthreads();
    unsigned qf[2][4][4];   // [mt][kk][frag]
    {
        unsigned bQ = uK[2];
#pragma unroll
        for (int kk = 0; kk < 4; kk++)
#pragma unroll
            for (int mt = 0; mt < 2; mt++) {
                int row = 32 * w + 16 * mt + (lane & 15);
                int ch  = 2 * kk + (lane >> 4);
                ldm_x4(bQ + swz(row, ch), qf[mt][kk][0], qf[mt][kk][1],
                       qf[mt][kk][2], qf[mt][kk][3]);
            }
    }
    // NOTE: stage 2 not overwritten until the cp.async issued inside iteration
    // kt=0, which happens after a __syncthreads() — Q frags are safe.

    // ---- Kick off pipeline: tiles 0 and 1 ----
#pragma unroll
    for (int p = 0; p < 2; p++) {
        const __half* Kp = Kb + (size_t)p * 64 * D_K;
        const __half* Vp = Vb + (size_t)p * 64 * D_K;
#pragma unroll
        for (int i = 0; i < 4; i++) {
            int row = arow + 16 * i;
            cp_async16(uK[p] + swz(row, ach), Kp + row * D_K + ach * 8);
            cp_async16(uV[p] + swz(row, ach), Vp + row * D_K + ach * 8);
        }
        CP_COMMIT();
    }

    float o[2][8][4];
#pragma unroll
    for (int mt = 0; mt < 2; mt++)
#pragma unroll
        for (int n = 0; n < 8; n++)
#pragma unroll
            for (int cc = 0; cc < 4; cc++) o[mt][n][cc] = 0.0f;
    float mrow[2][2] = {{-1e30f, -1e30f}, {-1e30f, -1e30f}};
    float lrow[2][2] = {{0.0f, 0.0f}, {0.0f, 0.0f}};

    for (int kt = 0; kt < NTILES; kt++) {
        const int st = kt % 3;
        const unsigned cK = uK[st];
        const unsigned cV = uV[st];

        // Tile kt must have arrived. (Groups complete in order; if kt+1 was
        // issued, allow it to remain in flight.)
        if (kt + 1 < NTILES) { CP_WAIT(1); } else { CP_WAIT(0); }
        __syncthreads();   // tile kt visible to all; all warps done with iter kt-1

        // Issue tile kt+2 into the stage freed by iteration kt-1.
        if (kt + 2 < NTILES) {
            const int st2 = (kt + 2) % 3;
            const __half* Kp = Kb + (size_t)(kt + 2) * 64 * D_K;
            const __half* Vp = Vb + (size_t)(kt + 2) * 64 * D_K;
#pragma unroll
            for (int i = 0; i < 4; i++) {
                int row = arow + 16 * i;
                cp_async16(uK[st2] + swz(row, ach), Kp + row * D_K + ach * 8);
                cp_async16(uV[st2] + swz(row, ach), Vp + row * D_K + ach * 8);
            }
            CP_COMMIT();
        }

        // ---- MMA1: S = Q * K^T (Q frags from registers) ----
        float s[2][8][4];
#pragma unroll
        for (int mt = 0; mt < 2; mt++)
#pragma unroll
            for (int n = 0; n < 8; n++)
#pragma unroll
                for (int cc = 0; cc < 4; cc++) s[mt][n][cc] = 0.0f;

#pragma unroll
        for (int kk = 0; kk < 4; kk++) {
#pragma unroll
            for (int nt2 = 0; nt2 < 4; nt2++) {
                unsigned b0, b1, b2, b3;
                int row = nt2 * 16 + ((lane >> 4) << 3) + (lane & 7);
                int ch  = 2 * kk + ((lane >> 3) & 1);
                ldm_x4(cK + swz(row, ch), b0, b1, b2, b3);
#pragma unroll
                for (int mt = 0; mt < 2; mt++) {
                    mma16816(s[mt][2 * nt2 + 0], qf[mt][kk], b0, b1);
                    mma16816(s[mt][2 * nt2 + 1], qf[mt][kk], b2, b3);
                }
            }
        }

        // ---- Online softmax (base-2; Q pre-scaled by 0.125*log2e) ----
        unsigned pa_lo[2][8], pa_hi[2][8];
#pragma unroll
        for (int mt = 0; mt < 2; mt++) {
            float mx0 = -1e30f, mx1 = -1e30f;
#pragma unroll
            for (int n = 0; n < 8; n++) {
                mx0 = fmaxf(mx0, fmaxf(s[mt][n][0], s[mt][n][1]));
                mx1 = fmaxf(mx1, fmaxf(s[mt][n][2], s[mt][n][3]));
            }
            mx0 = fmaxf(mx0, __shfl_xor_sync(0xffffffffu, mx0, 1));
            mx0 = fmaxf(mx0, __shfl_xor_sync(0xffffffffu, mx0, 2));
            mx1 = fmaxf(mx1, __shfl_xor_sync(0xffffffffu, mx1, 1));
            mx1 = fmaxf(mx1, __shfl_xor_sync(0xffffffffu, mx1, 2));

            float m0n = fmaxf(mrow[mt][0], mx0);
            float m1n = fmaxf(mrow[mt][1], mx1);
            float c0 = fast_exp2(mrow[mt][0] - m0n);
            float c1 = fast_exp2(mrow[mt][1] - m1n);
            mrow[mt][0] = m0n;
            mrow[mt][1] = m1n;

            float sum0 = 0.0f, sum1 = 0.0f;
#pragma unroll
            for (int n = 0; n < 8; n++) {
                float p0 = fast_exp2(s[mt][n][0] - m0n);
                float p1 = fast_exp2(s[mt][n][1] - m0n);
                float p2 = fast_exp2(s[mt][n][2] - m1n);
                float p3 = fast_exp2(s[mt][n][3] - m1n);
                sum0 += p0 + p1;
                sum1 += p2 + p3;
                __half2 lo = __floats2half2_rn(p0, p1);
                __half2 hi = __floats2half2_rn(p2, p3);
                pa_lo[mt][n] = *reinterpret_cast<unsigned*>(&lo);
                pa_hi[mt][n] = *reinterpret_cast<unsigned*>(&hi);
            }
            sum0 += __shfl_xor_sync(0xffffffffu, sum0, 1);
            sum0 += __shfl_xor_sync(0xffffffffu, sum0, 2);
            sum1 += __shfl_xor_sync(0xffffffffu, sum1, 1);
            sum1 += __shfl_xor_sync(0xffffffffu, sum1, 2);
            lrow[mt][0] = lrow[mt][0] * c0 + sum0;
            lrow[mt][1] = lrow[mt][1] * c1 + sum1;

#pragma unroll
            for (int n = 0; n < 8; n++) {
                o[mt][n][0] *= c0;
                o[mt][n][1] *= c0;
                o[mt][n][2] *= c1;
                o[mt][n][3] *= c1;
            }
        }

        // ---- MMA2: O += P * V ----
#pragma unroll
        for (int kk = 0; kk < 4; kk++) {
            unsigned aP[2][4];
#pragma unroll
            for (int mt = 0; mt < 2; mt++) {
                aP[mt][0] = pa_lo[mt][2 * kk];
                aP[mt][1] = pa_hi[mt][2 * kk];
                aP[mt][2] = pa_lo[mt][2 * kk + 1];
                aP[mt][3] = pa_hi[mt][2 * kk + 1];
            }
#pragma unroll
            for (int j2 = 0; j2 < 4; j2++) {
                unsigned b0, b1, b2, b3;
                int row = kk * 16 + (((lane >> 3) & 1) << 3) + (lane & 7);
                int ch  = 2 * j2 + (lane >> 4);
                ldm_x4_t(cV + swz(row, ch), b0, b1, b2, b3);
#pragma unroll
                for (int mt = 0; mt < 2; mt++) {
                    mma16816(o[mt][2 * j2 + 0], aP[mt], b0, b1);
                    mma16816(o[mt][2 * j2 + 1], aP[mt], b2, b3);
                }
            }
        }
    }

    // ---- Epilogue: normalize, write f16 to g_oh[(b*T + t)*512 + h*64 + d] ----
    const int b = bh >> 3;
    const int h = bh & 7;
#pragma unroll
    for (int mt = 0; mt < 2; mt++) {
#pragma unroll
        for (int r01 = 0; r01 < 2; r01++) {
            int t = qt * 128 + 32 * w + 16 * mt + gid + 8 * r01;
            float inv = 1.0f / lrow[mt][r01];
            __half* op = &g_oh[((size_t)(b * T_SEQ + t)) * D_MODEL + h * D_K];
#pragma unroll
            for (int n = 0; n < 8; n++) {
                __half2 hv = __floats2half2_rn(o[mt][n][2 * r01 + 0] * inv,
                                               o[mt][n][2 * r01 + 1] * inv);
                *(__half2*)(op + n * 8 + 2 * tig) = hv;
            }
        }
    }
}

// ===========================================================================
// Launch
// ===========================================================================
extern "C" void kernel_launch(void* const* d_in, const int* in_sizes, int n_in,
                              void* d_out, int out_size)
{
    const float* x  = (const float*)d_in[0];
    const float* Wq = (const float*)d_in[1];
    const float* bq = (const float*)d_in[2];
    const float* Wk = (const float*)d_in[3];
    const float* bk = (const float*)d_in[4];
    const float* Wv = (const float*)d_in[5];
    const float* bv = (const float*)d_in[6];
    const float* Wo = (const float*)d_in[7];
    const float* bo = (const float*)d_in[8];
    float* out = (float*)d_out;

    f2h_x_kernel<<<512, 256>>>(x, (M_ROWS * D_MODEL) / 4);
    f2h_w_kernel<<<dim3(64, 4, 1), 256>>>(Wq, Wk, Wv, Wo);

    dim3 blk(128, 1, 1);
    gemm_qkv_kernel<<<dim3(D_MODEL / 64, M_ROWS / 128, 3), blk>>>(bq, bk, bv);

    attn_mma_kernel<<<dim3(T_SEQ / 128, BH, 1), blk>>>();

    gemm_o_kernel<<<dim3(D_MODEL / 64, M_ROWS / 128, 1), blk>>>(bo, out);
}